// round 16
// baseline (speedup 1.0000x reference)
#include <cuda_runtime.h>
#include <math.h>
#include <stdint.h>

#define B_ 64
#define T_ 1024
#define D_ 256
#define H_ 512
#define O_ 256

#define GROUPS 16
#define CPG 8              // CTAs per group (column split of H)
#define BPG (B_ / GROUPS)  // 4 batches per group
#define COLS (H_ / CPG)    // 64 output columns per CTA

typedef unsigned long long ull;

// Scratch (static device allocations; runtime alloc is forbidden)
__device__ float g_xw[(size_t)B_ * T_ * H_];   // 128 MB: xW0, later reused as xW1
__device__ float g_seq[(size_t)B_ * T_ * H_];  // 128 MB: layer-0 outputs
// Exchange pairs {float h, uint stamp} packed in 8B (single-copy atomic:
// data + validity in ONE access). Double-buffered by timestep parity.
__device__ ull g_hp[2][GROUPS][BPG][H_];
// Monotonic per-group stamp base; advanced by T_ per scan launch.
__device__ unsigned g_base[GROUPS];

// ---------------------------------------------------------------------------
// Packed fp32x2 helpers (exact fp32 math, 2 FMAs per instruction)
// ---------------------------------------------------------------------------
__device__ __forceinline__ ull ffma2(ull a, ull b, ull c) {
    ull d;
    asm("fma.rn.f32x2 %0, %1, %2, %3;" : "=l"(d) : "l"(a), "l"(b), "l"(c));
    return d;
}
__device__ __forceinline__ ull addf2(ull a, ull b) {
    ull d;
    asm("add.rn.f32x2 %0, %1, %2;" : "=l"(d) : "l"(a), "l"(b));
    return d;
}
__device__ __forceinline__ ull pk2(float x, float y) {
    ull r;
    asm("mov.b64 %0, {%1, %2};" : "=l"(r) : "f"(x), "f"(y));
    return r;
}
__device__ __forceinline__ float2 unpk(ull a) {
    float2 f;
    asm("mov.b64 {%0, %1}, %2;" : "=f"(f.x), "=f"(f.y) : "l"(a));
    return f;
}
__device__ __forceinline__ ull ldpair(const ull* p) {
    ull v;
    asm volatile("ld.global.cg.u64 %0, [%1];" : "=l"(v) : "l"(p) : "memory");
    return v;
}
__device__ __forceinline__ void nsleep(unsigned ns) {
    asm volatile("nanosleep.u32 %0;" :: "r"(ns));
}

// ---------------------------------------------------------------------------
// tf32 tensor-core GEMM, 2-STAGE PIPELINED:
//   per K-tile: LDG(i+1)->regs | MMA on smem[buf] | STS(i+1)->smem[buf^1] | bar
// DRAM latency hidden under MMA; ONE barrier per tile (was 2 + naked latency).
// C[M,N] = A[M,K] @ B[N,K]^T + b1[N] + b2[N]; 128x128 tile, BK=32, 256 thr.
// ---------------------------------------------------------------------------
__device__ __forceinline__ unsigned f2tf32(float f) {
    unsigned r;
    asm("cvt.rna.tf32.f32 %0, %1;" : "=r"(r) : "f"(f));
    return r;
}
__device__ __forceinline__ void mma_tf32(float* c, unsigned a0, unsigned a1,
                                         unsigned a2, unsigned a3,
                                         unsigned b0, unsigned b1) {
    asm volatile(
        "mma.sync.aligned.m16n8k8.row.col.f32.tf32.tf32.f32 "
        "{%0,%1,%2,%3}, {%4,%5,%6,%7}, {%8,%9}, {%0,%1,%2,%3};\n"
        : "+f"(c[0]), "+f"(c[1]), "+f"(c[2]), "+f"(c[3])
        : "r"(a0), "r"(a1), "r"(a2), "r"(a3), "r"(b0), "r"(b1));
}

__global__ void __launch_bounds__(256) gemm_tf32(
    const float* __restrict__ A, const float* __restrict__ Bm,
    const float* __restrict__ b1, const float* __restrict__ b2,
    float* __restrict__ C, int M, int N, int K)
{
    __shared__ unsigned Asm[2][128 * 36];
    __shared__ unsigned Bsm[2][128 * 36];

    const int m0 = blockIdx.y * 128;
    const int n0 = blockIdx.x * 128;
    const int tid = threadIdx.x;
    const int lane = tid & 31;
    const int wid = tid >> 5;
    const int wm = wid & 3;
    const int wn = wid >> 2;
    const int l4 = lane >> 2;
    const int lm = lane & 3;

    // loader mapping: 4 slots x (row = qg>>3, quad q = qg&7)
    int lrow[4], lq[4];
#pragma unroll
    for (int i = 0; i < 4; i++) {
        int qg = tid + 256 * i;
        lrow[i] = qg >> 3;
        lq[i]   = qg & 7;
    }

    float acc[2][8][4];
#pragma unroll
    for (int i = 0; i < 2; i++)
#pragma unroll
        for (int j = 0; j < 8; j++)
#pragma unroll
            for (int k = 0; k < 4; k++) acc[i][j][k] = 0.f;

    const int ntile = K >> 5;
    float4 stgA[4], stgB[4];

    // prologue: load tile 0 -> regs -> smem[0]
#pragma unroll
    for (int i = 0; i < 4; i++) {
        stgA[i] = *(const float4*)(A + (size_t)(m0 + lrow[i]) * K + lq[i] * 4);
        stgB[i] = *(const float4*)(Bm + (size_t)(n0 + lrow[i]) * K + lq[i] * 4);
    }
#pragma unroll
    for (int i = 0; i < 4; i++) {
        unsigned* da = &Asm[0][lrow[i] * 36 + lq[i] * 4];
        da[0] = f2tf32(stgA[i].x); da[1] = f2tf32(stgA[i].y);
        da[2] = f2tf32(stgA[i].z); da[3] = f2tf32(stgA[i].w);
        unsigned* db = &Bsm[0][lrow[i] * 36 + lq[i] * 4];
        db[0] = f2tf32(stgB[i].x); db[1] = f2tf32(stgB[i].y);
        db[2] = f2tf32(stgB[i].z); db[3] = f2tf32(stgB[i].w);
    }
    __syncthreads();

    int buf = 0;
    for (int it = 0; it < ntile; it++) {
        // issue loads for tile it+1 (latency hidden under the MMAs below)
        if (it + 1 < ntile) {
            int k0 = (it + 1) << 5;
#pragma unroll
            for (int i = 0; i < 4; i++) {
                stgA[i] = *(const float4*)(A + (size_t)(m0 + lrow[i]) * K + k0 + lq[i] * 4);
                stgB[i] = *(const float4*)(Bm + (size_t)(n0 + lrow[i]) * K + k0 + lq[i] * 4);
            }
        }

        // MMA on smem[buf]
#pragma unroll
        for (int ks = 0; ks < 4; ks++) {
            unsigned a[2][4];
#pragma unroll
            for (int mt = 0; mt < 2; mt++) {
                const unsigned* ap = &Asm[buf][(wm * 32 + mt * 16 + l4) * 36 + ks * 8 + lm];
                a[mt][0] = ap[0];
                a[mt][1] = ap[8 * 36];
                a[mt][2] = ap[4];
                a[mt][3] = ap[8 * 36 + 4];
            }
#pragma unroll
            for (int nt = 0; nt < 8; nt++) {
                const unsigned* bp = &Bsm[buf][(wn * 64 + nt * 8 + l4) * 36 + ks * 8 + lm];
                unsigned b0 = bp[0];
                unsigned b1v = bp[4];
                mma_tf32(acc[0][nt], a[0][0], a[0][1], a[0][2], a[0][3], b0, b1v);
                mma_tf32(acc[1][nt], a[1][0], a[1][1], a[1][2], a[1][3], b0, b1v);
            }
        }

        if (it + 1 < ntile) {
            // store tile it+1 into the other buffer (its last readers finished
            // before the barrier at the end of iteration it-1)
#pragma unroll
            for (int i = 0; i < 4; i++) {
                unsigned* da = &Asm[buf ^ 1][lrow[i] * 36 + lq[i] * 4];
                da[0] = f2tf32(stgA[i].x); da[1] = f2tf32(stgA[i].y);
                da[2] = f2tf32(stgA[i].z); da[3] = f2tf32(stgA[i].w);
                unsigned* db = &Bsm[buf ^ 1][lrow[i] * 36 + lq[i] * 4];
                db[0] = f2tf32(stgB[i].x); db[1] = f2tf32(stgB[i].y);
                db[2] = f2tf32(stgB[i].z); db[3] = f2tf32(stgB[i].w);
            }
            __syncthreads();   // stores visible + all MMAs on smem[buf] done
            buf ^= 1;
        }
    }

#pragma unroll
    for (int nt = 0; nt < 8; nt++) {
        int n = n0 + wn * 64 + nt * 8 + 2 * lm;
        float bv0 = b1[n] + b2[n];
        float bv1 = b1[n + 1] + b2[n + 1];
#pragma unroll
        for (int mt = 0; mt < 2; mt++) {
            int r = m0 + wm * 32 + mt * 16 + l4;
            float2 v0 = make_float2(acc[mt][nt][0] + bv0, acc[mt][nt][1] + bv1);
            float2 v1 = make_float2(acc[mt][nt][2] + bv0, acc[mt][nt][3] + bv1);
            *(float2*)(C + (size_t)r * N + n) = v0;
            *(float2*)(C + (size_t)(r + 8) * N + n) = v1;
        }
    }
}

// ---------------------------------------------------------------------------
// Persistent recurrent scan: BATCH-ROTATED pipeline, pair-wise resolve,
// PURE-SPIN resolve (no nanosleep: expected wait is ~1 L2 RTT; 4-load spin is
// ~3.4 KB/cyc chip-wide, well under the LTS cap).
// ---------------------------------------------------------------------------
template <bool STORE_SEQ, bool FUSE_FC>
__global__ void __launch_bounds__(256) scan_kernel(
    const float* __restrict__ Whh,
    const float* __restrict__ Wfc, const float* __restrict__ bfc,
    float* __restrict__ out)
{
    // hb[par][b][ks][132]: 528B row stride -> conflict-free broadcast LDS.
    __shared__ __align__(16) float hb[2][BPG][4][132];
    __shared__ unsigned sv0;

    const int tid = threadIdx.x;
    const int g = blockIdx.x >> 3;
    const int c = blockIdx.x & 7;

    const int w_id = tid >> 5;
    const int lane = tid & 31;
    const int colL = w_id * 8 + (lane & 7);   // column within CTA slice
    const int ks   = lane >> 3;               // k-slice 0..3 (128 k each)
    const int jglob = c * COLS + colL;
    const bool emitter = (lane < 8);          // lanes 0-7 own the final sums

    // ---- W slice into registers: W[jglob][ks*128 .. +128) as 64 b64 k-pairs
    ull wr[64];
    {
        const float4* wp = (const float4*)(Whh + (size_t)jglob * H_ + ks * 128);
#pragma unroll
        for (int i = 0; i < 32; i++) {
            float4 v = wp[i];
            wr[2 * i]     = pk2(v.x, v.y);
            wr[2 * i + 1] = pk2(v.z, v.w);
        }
    }

    if (tid == 0) sv0 = g_base[g];
    for (int i = tid; i < 2 * BPG * 4 * 132; i += 256) (&hb[0][0][0][0])[i] = 0.f;

    // xw pipeline: load t=0 now
    float xw_cur[4], xw_nxt[4];
#pragma unroll
    for (int b = 0; b < BPG; b++) xw_nxt[b] = 0.f;
    if (emitter) {
#pragma unroll
        for (int b = 0; b < BPG; b++)
            xw_nxt[b] = __ldcg(&g_xw[(size_t)(g * BPG + b) * T_ * H_ + jglob]);
    }
    __syncthreads();
    const unsigned v0 = sv0;

    // inflight polls for the next PAIR: pr[0..1] batch nb, pr[2..3] batch nb+1
    ull pr[4] = {0, 0, 0, 0};
    const ull* pa0 = &g_hp[0][g][0][tid];
    const ull* pa1 = &g_hp[0][g][1][tid];

    for (int t = 0; t < T_; t++) {
        const int dpar = (t + 1) & 1;           // parity holding h(t-1)
        const unsigned want = v0 + (unsigned)t; // stamp of h(t-1)

        // rotate xw pipeline; issue loads for t+1
#pragma unroll
        for (int b = 0; b < BPG; b++) xw_cur[b] = xw_nxt[b];
        if (emitter && (t + 1 < T_)) {
#pragma unroll
            for (int b = 0; b < BPG; b++)
                xw_nxt[b] = __ldcg(&g_xw[((size_t)(g * BPG + b) * T_ + (t + 1)) * H_ + jglob]);
        }

#pragma unroll
        for (int bp = 0; bp < BPG; bp += 2) {
            if (t > 0) {
                // resolve prefetched polls for batches bp, bp+1 at h(t-1)
                bool d0 = ((unsigned)(pr[0] >> 32) == want);
                bool d1 = ((unsigned)(pr[1] >> 32) == want);
                bool d2 = ((unsigned)(pr[2] >> 32) == want);
                bool d3 = ((unsigned)(pr[3] >> 32) == want);
                while (!(d0 && d1 && d2 && d3)) {
                    if (!d0) { pr[0] = ldpair(pa0);       d0 = ((unsigned)(pr[0] >> 32) == want); }
                    if (!d1) { pr[1] = ldpair(pa0 + 256); d1 = ((unsigned)(pr[1] >> 32) == want); }
                    if (!d2) { pr[2] = ldpair(pa1);       d2 = ((unsigned)(pr[2] >> 32) == want); }
                    if (!d3) { pr[3] = ldpair(pa1 + 256); d3 = ((unsigned)(pr[3] >> 32) == want); }
                }
                float f0 = __uint_as_float((unsigned)(pr[0] & 0xffffffffull));
                float f1 = __uint_as_float((unsigned)(pr[1] & 0xffffffffull));
                float f2 = __uint_as_float((unsigned)(pr[2] & 0xffffffffull));
                float f3 = __uint_as_float((unsigned)(pr[3] & 0xffffffffull));
                hb[dpar][bp][tid >> 7][tid & 127] = f0;
                hb[dpar][bp][(tid >> 7) + 2][tid & 127] = f1;
                hb[dpar][bp + 1][tid >> 7][tid & 127] = f2;
                hb[dpar][bp + 1][(tid >> 7) + 2][tid & 127] = f3;
                if (STORE_SEQ) {
                    // consumer-side sequence store (coalesced, off emit path)
                    float* s0 = &g_seq[((size_t)(g * BPG + bp) * T_ + (t - 1)) * H_];
                    float* s1 = &g_seq[((size_t)(g * BPG + bp + 1) * T_ + (t - 1)) * H_];
                    __stcg(s0 + tid, f0);
                    __stcg(s0 + tid + 256, f1);
                    __stcg(s1 + tid, f2);
                    __stcg(s1 + tid + 256, f3);
                }
                __syncthreads();
            }

            // prefetch polls for the next pair
            {
                int nb, pq;
                if (bp == 0) { nb = 2; pq = dpar; }      // pair (t, 2)
                else         { nb = 0; pq = t & 1; }     // pair (t+1, 0)
                pa0 = &g_hp[pq][g][nb][tid];
                pa1 = &g_hp[pq][g][nb + 1][tid];
                pr[0] = ldpair(pa0);
                pr[1] = ldpair(pa0 + 256);
                pr[2] = ldpair(pa1);
                pr[3] = ldpair(pa1 + 256);
            }

            // GEMM + emit for the two batches of this pair
#pragma unroll
            for (int u = 0; u < 2; u++) {
                const int b = bp + u;
                const ulonglong2* hp = (const ulonglong2*)&hb[dpar][b][ks][0];
                ull A = 0ull, Bc = 0ull;
#pragma unroll
                for (int q = 0; q < 32; q++) {
                    ulonglong2 v = hp[q];
                    A  = ffma2(wr[2 * q],     v.x, A);
                    Bc = ffma2(wr[2 * q + 1], v.y, Bc);
                }
                float2 uu = unpk(addf2(A, Bc));
                float s = uu.x + uu.y;
                s += __shfl_xor_sync(0xffffffffu, s, 8);
                s += __shfl_xor_sync(0xffffffffu, s, 16);

                if (emitter) {
                    float hn = tanhf(s + xw_cur[b]);
                    if ((t < T_ - 1) || FUSE_FC) {
                        __stcg(&g_hp[t & 1][g][b][jglob],
                               ((ull)(want + 1u) << 32) | (ull)__float_as_uint(hn));
                    } else if (STORE_SEQ) {
                        // t = T-1 in scan0: never exchanged; store directly once
                        __stcg(&g_seq[((size_t)(g * BPG + b) * T_ + t) * H_ + jglob], hn);
                    }
                }
            }
        }
    }

    if (FUSE_FC) {
        __syncthreads();   // last GEMM reads of hb[0] complete before reuse
        const unsigned wantT = v0 + (unsigned)T_;
        const int qp = (T_ - 1) & 1;
#pragma unroll
        for (int b = 0; b < BPG; b++) {
            const ull* a = &g_hp[qp][g][b][tid];
            ull r0 = ldpair(a), r1 = ldpair(a + 256);
            bool d0 = ((unsigned)(r0 >> 32) == wantT);
            bool d1 = ((unsigned)(r1 >> 32) == wantT);
            while (!(d0 && d1)) {
                if (!d0) { r0 = ldpair(a);       d0 = ((unsigned)(r0 >> 32) == wantT); }
                if (!d1) { r1 = ldpair(a + 256); d1 = ((unsigned)(r1 >> 32) == wantT); }
            }
            hb[0][b][tid >> 7][tid & 127] =
                __uint_as_float((unsigned)(r0 & 0xffffffffull));
            hb[0][b][(tid >> 7) + 2][tid & 127] =
                __uint_as_float((unsigned)(r1 & 0xffffffffull));
        }
        __syncthreads();
        if (tid < 128) {
            int b = tid >> 5;
            int nl = tid & 31;
            int n = c * (O_ / CPG) + nl;
            const float* wf = Wfc + (size_t)n * H_;
            float acc = 0.f;
#pragma unroll 8
            for (int k4 = 0; k4 < H_ / 4; k4++) {
                float4 a = *(const float4*)(wf + k4 * 4);
                float4 x = *(const float4*)&hb[0][b][k4 >> 5][(k4 & 31) * 4];
                acc += a.x * x.x + a.y * x.y + a.z * x.z + a.w * x.w;
            }
            out[(g * BPG + b) * O_ + n] = acc + bfc[n];
        }
    }

    // advance stamp base for next launch (monotonic, replay-safe)
    if (c == 0 && tid == 0) g_base[g] = v0 + (unsigned)T_;
}

// ---------------------------------------------------------------------------

extern "C" void kernel_launch(void* const* d_in, const int* in_sizes, int n_in,
                              void* d_out, int out_size)
{
    const float* x     = (const float*)d_in[0];
    const float* W_ih0 = (const float*)d_in[1];
    const float* W_hh0 = (const float*)d_in[2];
    const float* b_ih0 = (const float*)d_in[3];
    const float* b_hh0 = (const float*)d_in[4];
    const float* W_ih1 = (const float*)d_in[5];
    const float* W_hh1 = (const float*)d_in[6];
    const float* b_ih1 = (const float*)d_in[7];
    const float* b_hh1 = (const float*)d_in[8];
    const float* W_fc  = (const float*)d_in[9];
    const float* b_fc  = (const float*)d_in[10];
    float* out = (float*)d_out;

    void* p_xw = nullptr;
    void* p_seq = nullptr;
    cudaGetSymbolAddress(&p_xw, g_xw);
    cudaGetSymbolAddress(&p_seq, g_seq);

    const int MT = B_ * T_;  // 65536

    // Layer 0 input projection: g_xw = x @ W_ih0^T + b_ih0 + b_hh0
    gemm_tf32<<<dim3(H_ / 128, MT / 128), 256>>>(
        x, W_ih0, b_ih0, b_hh0, (float*)p_xw, MT, H_, D_);

    // Layer 0 scan -> g_seq
    scan_kernel<true, false><<<GROUPS * CPG, 256>>>(
        W_hh0, nullptr, nullptr, nullptr);

    // Layer 1 input projection: g_xw = g_seq @ W_ih1^T + b_ih1 + b_hh1
    gemm_tf32<<<dim3(H_ / 128, MT / 128), 256>>>(
        (const float*)p_seq, W_ih1, b_ih1, b_hh1, (float*)p_xw, MT, H_, H_);

    // Layer 1 scan + fused fc -> out
    scan_kernel<false, true><<<GROUPS * CPG, 256>>>(
        W_hh1, W_fc, b_fc, out);
}